// round 13
// baseline (speedup 1.0000x reference)
#include <cuda_runtime.h>
#include <cstdint>

// EquiLocalPatOrientConvolution: B=2, I=32, O=64, D=H=W=48, K=5 (pad 2).
// v13 = v12 (quad packing, 2-split tf32 mma) with in-load x-presummation:
// 144 half-row tasks LDG->presum(s0/s1/s4)->STS S; stageB gathers 75 (not
// 125) LDS.128 per voxel. Same 2-barrier phase discipline. 4 blocks/SM.

#define DIMS  48
#define TX    8
#define TY    8
#define TZ    2
#define HX    12
#define HY    12
#define HZ    6
#define NI    32
#define NO    64
#define NP    10
#define Y0C   0.28209479177387814f
#define NTHR  128
#define NQUAD 8
#define NKS   5                          // k8 steps per quad (K=40)

#define SSTR4      73                    // S stride in float4 (odd -> conflict-free)
#define S_FLOAT4   (24 * SSTR4)          // 3 classes x 8 xpos -> 24 cols of 72 (+pad)
#define YS_STRIDE  136                   // 128 vox + 8 pad
#define SMEM_FLOATS (4 * S_FLOAT4 + 40 * YS_STRIDE)   // 7008 + 5440 = 12448
#define SMEM_BYTES  (SMEM_FLOATS * 4 + 256)           // ~50 KB -> 4 blocks/SM

typedef unsigned long long ull_t;

__device__ __host__ constexpr int p_of_r2(int r2) {
    return r2 <= 6 ? r2 : (r2 == 8 ? 7 : (r2 == 9 ? 8 : 9));
}

// B fragments: [quad][ks][nt][lane] -> float2 {b0hi, b1hi}
__device__ float2 g_Bf[NQUAD * NKS * 8 * 32];

__device__ __forceinline__ uint32_t tf32_rna(float x) {
    uint32_t r;
    asm("cvt.rna.tf32.f32 %0, %1;" : "=r"(r) : "f"(x));
    return r;
}

__device__ __forceinline__ ull_t addx2(ull_t a, ull_t b) {
    ull_t r;
    asm("add.rn.f32x2 %0, %1, %2;" : "=l"(r) : "l"(a), "l"(b));
    return r;
}

__device__ __forceinline__ void mma_tf32(float* c,
                                         uint32_t a0, uint32_t a1, uint32_t a2, uint32_t a3,
                                         uint32_t b0, uint32_t b1) {
    asm("mma.sync.aligned.m16n8k8.row.col.f32.tf32.tf32.f32 "
        "{%0,%1,%2,%3}, {%4,%5,%6,%7}, {%8,%9}, {%0,%1,%2,%3};"
        : "+f"(c[0]), "+f"(c[1]), "+f"(c[2]), "+f"(c[3])
        : "r"(a0), "r"(a1), "r"(a2), "r"(a3), "r"(b0), "r"(b1));
}

// ---------- prep: W[o][ci][p] -> B-fragment layout, Y0 folded, hi tf32 ----------
__global__ void bprep_kernel(const float* __restrict__ wg) {
    int idx = blockIdx.x * 256 + threadIdx.x;
    if (idx >= NQUAD * NKS * 8 * 32) return;
    int lane = idx & 31;
    int r    = idx >> 5;
    int nt   = r & 7;  r >>= 3;
    int ks   = r % NKS;
    int quad = r / NKS;
    int gid = lane >> 2, tidg = lane & 3;
    int o = nt * 8 + gid;
    auto getw = [&](int k) -> float {        // k in 0..39
        int ci = quad * 4 + k / 10;
        int p  = k % 10;
        return Y0C * wg[o * (NI * NP) + ci * NP + p];
    };
    float b0 = getw(ks * 8 + tidg);
    float b1 = getw(ks * 8 + tidg + 4);
    g_Bf[idx] = make_float2(__uint_as_float(tf32_rna(b0)),
                            __uint_as_float(tf32_rna(b1)));
}

// ---------- main ----------
__global__ void __launch_bounds__(NTHR, 4)
econv_kernel(const float* __restrict__ x,
             const float* __restrict__ bias,
             float* __restrict__ out)
{
    extern __shared__ float smem[];
    float4* S4 = (float4*)smem;                 // [(cls*8+xpos)*SSTR4 + zy]
    float*  Ys = smem + 4 * S_FLOAT4;           // [k][vox], stride YS_STRIDE

    const int tid  = threadIdx.x;
    const int wid  = tid >> 5;
    const int lid  = tid & 31;
    const int gid  = lid >> 2;
    const int tidg = lid & 3;
    const int b    = blockIdx.y;
    const int t    = blockIdx.x;                // 6x6x24
    const int tz   = t / 36;
    const int ty   = (t % 36) / 6;
    const int tx   = t % 6;
    const int z0   = tz * TZ, y0 = ty * TY, x0 = tx * TX;

    const size_t x_chan = (size_t)DIMS * DIMS * DIMS;
    const float* xb = x + (size_t)b * NI * x_chan;

    float acc[64];
    #pragma unroll
    for (int k = 0; k < 64; k++) acc[k] = 0.0f;

    // ---- one half-row presum task: LDG 8 cells -> s0/s1/s4 -> STS S ----
    auto do_task = [&](const float* c0, int task) {
        const int row  = task >> 1;             // zy in 0..71
        const int half = task & 1;
        const int zz   = row / HY, yy = row % HY;
        const int gz   = z0 + zz - 2, gy = y0 + yy - 2;
        const bool zyok = ((unsigned)gz < (unsigned)DIMS) &&
                          ((unsigned)gy < (unsigned)DIMS);
        const int gx0  = x0 - 2 + half * 4;
        ull_t c01[8], c23[8];
        #pragma unroll
        for (int j = 0; j < 8; j++) {
            float v0 = 0.f, v1 = 0.f, v2 = 0.f, v3 = 0.f;
            int gx = gx0 + j;
            if (zyok && (unsigned)gx < (unsigned)DIMS) {
                size_t off = ((size_t)gz * DIMS + gy) * DIMS + gx;
                v0 = __ldg(&c0[off]);
                v1 = __ldg(&c0[off + x_chan]);
                v2 = __ldg(&c0[off + 2 * x_chan]);
                v3 = __ldg(&c0[off + 3 * x_chan]);
            }
            float2 lo = make_float2(v0, v1), hi = make_float2(v2, v3);
            c01[j] = *(ull_t*)&lo;
            c23[j] = *(ull_t*)&hi;
        }
        #pragma unroll
        for (int k = 0; k < 4; k++) {
            const int pos = half * 4 + k;
            union { ull_t u[2]; float4 f; } s0, s1, s4;
            s0.u[0] = c01[k + 2];               s0.u[1] = c23[k + 2];
            s1.u[0] = addx2(c01[k + 1], c01[k + 3]);
            s1.u[1] = addx2(c23[k + 1], c23[k + 3]);
            s4.u[0] = addx2(c01[k], c01[k + 4]);
            s4.u[1] = addx2(c23[k], c23[k + 4]);
            S4[(0 * 8 + pos) * SSTR4 + row] = s0.f;
            S4[(1 * 8 + pos) * SSTR4 + row] = s1.f;
            S4[(2 * 8 + pos) * SSTR4 + row] = s4.f;
        }
    };
    auto presum = [&](int quad) {
        const float* c0 = xb + (size_t)(4 * quad) * x_chan;
        do_task(c0, tid);
        if (tid < 144 - NTHR) do_task(c0, NTHR + tid);
    };

    // ---- stage B: 75 LDS.128 gather -> Ys (10 classes x 4 channels) ----
    auto stageB = [&]() {
        const int vz = tid >> 6, vy = (tid >> 3) & 7, vx = tid & 7;
        const float4* Sc0 = S4 + (0 * 8 + vx) * SSTR4;
        const float4* Sc1 = S4 + (1 * 8 + vx) * SSTR4;
        const float4* Sc2 = S4 + (2 * 8 + vx) * SSTR4;
        ull_t y01[NP], y23[NP];
        #pragma unroll
        for (int p = 0; p < NP; p++) { y01[p] = 0ULL; y23[p] = 0ULL; }
        #pragma unroll
        for (int dz = 0; dz < 5; dz++) {
            #pragma unroll
            for (int dy = 0; dy < 5; dy++) {
                const int q2 = (dz - 2) * (dz - 2) + (dy - 2) * (dy - 2);
                const int zy = (vz + dz) * HY + (vy + dy);
                union { float4 f; ull_t u[2]; } a0, a1, a2;
                a0.f = Sc0[zy];
                a1.f = Sc1[zy];
                a2.f = Sc2[zy];
                const int p0 = p_of_r2(q2), p1 = p_of_r2(q2 + 1), p4 = p_of_r2(q2 + 4);
                y01[p0] = addx2(y01[p0], a0.u[0]); y23[p0] = addx2(y23[p0], a0.u[1]);
                y01[p1] = addx2(y01[p1], a1.u[0]); y23[p1] = addx2(y23[p1], a1.u[1]);
                y01[p4] = addx2(y01[p4], a2.u[0]); y23[p4] = addx2(y23[p4], a2.u[1]);
            }
        }
        #pragma unroll
        for (int p = 0; p < NP; p++) {
            float2 a = *(float2*)&y01[p];
            float2 d = *(float2*)&y23[p];
            Ys[p * YS_STRIDE + tid]        = a.x;   // ch0 -> k rows 0..9
            Ys[(p + 10) * YS_STRIDE + tid] = a.y;   // ch1 -> k rows 10..19
            Ys[(p + 20) * YS_STRIDE + tid] = d.x;   // ch2 -> k rows 20..29
            Ys[(p + 30) * YS_STRIDE + tid] = d.y;   // ch3 -> k rows 30..39
        }
    };

    // ---- GEMM: 2-split tf32 mma over this quad's K=40 (5 exact k8 steps) ----
    auto gemm = [&](int quad) {
        const float2* bsrc = g_Bf + quad * (NKS * 8 * 32);
        #pragma unroll
        for (int ks = 0; ks < NKS; ks++) {
            uint32_t Ah[2][4], Al[2][4];
            #pragma unroll
            for (int mt = 0; mt < 2; mt++) {
                const int vb = wid * 32 + mt * 16 + gid;
                const float* yk = Ys + (ks * 8 + tidg) * YS_STRIDE;
                float a[4];
                a[0] = yk[vb];
                a[1] = yk[vb + 8];
                a[2] = yk[4 * YS_STRIDE + vb];
                a[3] = yk[4 * YS_STRIDE + vb + 8];
                #pragma unroll
                for (int r = 0; r < 4; r++) {
                    Ah[mt][r] = tf32_rna(a[r]);
                    Al[mt][r] = tf32_rna(a[r] - __uint_as_float(Ah[mt][r]));
                }
            }
            #pragma unroll
            for (int nt = 0; nt < 8; nt++) {
                float2 bf = __ldg(&bsrc[(ks * 8 + nt) * 32 + lid]);
                uint32_t b0h = __float_as_uint(bf.x);
                uint32_t b1h = __float_as_uint(bf.y);
                #pragma unroll
                for (int mt = 0; mt < 2; mt++) {
                    float* c = &acc[(mt * 8 + nt) * 4];
                    mma_tf32(c, Ah[mt][0], Ah[mt][1], Ah[mt][2], Ah[mt][3], b0h, b1h);
                    mma_tf32(c, Al[mt][0], Al[mt][1], Al[mt][2], Al[mt][3], b0h, b1h);
                }
            }
        }
    };

    // ---- prologue ----
    presum(0);
    __syncthreads();                 // S(0) visible
    stageB();                        // Ys(0)

    // ---- main loop over 8 quads (2 bars/iter, phase-pure regions) ----
    #pragma unroll 1
    for (int q = 0; q < NQUAD; q++) {
        __syncthreads();             // Ys(q) visible
        gemm(q);
        if (q + 1 < NQUAD) {
            presum(q + 1);           // writes S(q+1); disjoint from Ys(q)
            __syncthreads();         // S(q+1) visible; gemm done with Ys
            stageB();                // Ys(q+1)
        }
    }

    // ---- epilogue: stage through smem (aliases Ys) for coalesced stores ----
    __syncthreads();
    float* stage = Ys;
    #pragma unroll 1
    for (int chunk = 0; chunk < 4; chunk++) {
        if (chunk) __syncthreads();
        #pragma unroll
        for (int mt = 0; mt < 2; mt++) {
            #pragma unroll
            for (int nt2 = 0; nt2 < 2; nt2++) {
                const int nt = chunk * 2 + nt2;
                #pragma unroll
                for (int r = 0; r < 4; r++) {
                    int vox = wid * 32 + mt * 16 + gid + ((r >> 1) << 3);
                    int c16 = nt2 * 8 + 2 * tidg + (r & 1);
                    stage[c16 * YS_STRIDE + vox] = acc[(mt * 8 + nt) * 4 + r];
                }
            }
        }
        __syncthreads();
        #pragma unroll
        for (int j = 0; j < 4; j++) {
            const int o16  = j * 4 + wid;
            const int row  = lid >> 1;
            const int half = lid & 1;
            const int o    = chunk * 16 + o16;
            const float bb = __ldg(&bias[o]);
            float4 v = *(float4*)&stage[o16 * YS_STRIDE + row * 8 + half * 4];
            v.x += bb; v.y += bb; v.z += bb; v.w += bb;
            const int gz = z0 + (row >> 3), gy = y0 + (row & 7);
            float* dst = out + ((size_t)b * NO + o) * x_chan
                             + ((size_t)gz * DIMS + gy) * DIMS + x0 + half * 4;
            *(float4*)dst = v;
        }
    }
}

extern "C" void kernel_launch(void* const* d_in, const int* in_sizes, int n_in,
                              void* d_out, int out_size)
{
    const float* x    = (const float*)d_in[0];   // [2,32,1,48,48,48]
    const float* w    = (const float*)d_in[1];   // [64,32,1,1,1,10]
    const float* bias = (const float*)d_in[2];   // [64]
    float* out = (float*)d_out;                  // [2,64,1,48,48,48]

    bprep_kernel<<<(NQUAD * NKS * 8 * 32 + 255) / 256, 256>>>(w);

    cudaFuncSetAttribute(econv_kernel,
                         cudaFuncAttributeMaxDynamicSharedMemorySize, SMEM_BYTES);
    dim3 grid(864, 2);   // 6x6x24 spatial tiles x batch
    econv_kernel<<<grid, NTHR, SMEM_BYTES>>>(x, bias, out);
}

// round 14
// speedup vs baseline: 1.1251x; 1.1251x over previous
#include <cuda_runtime.h>
#include <cstdint>

// EquiLocalPatOrientConvolution: B=2, I=32, O=64, D=H=W=48, K=5 (pad 2).
// v14 = v12 algorithm (quad packing, direct conflict-free radial, 2-split
// tf32 mma) at 64-voxel tiles: acc 64->32 regs, smem ~35KB, 6 blocks/SM
// (24 warps) for crossbar latency hiding. rel_err ~2e-4.

#define DIMS  48
#define TX    8
#define TY    8
#define HXX   12
#define HYY   12
#define HZZ   5                          // TZ=1 -> 5 z-rows
#define XSTR  24                         // xs row stride (float2), conflict-free
#define NI    32
#define NO    64
#define NP    10
#define Y0C   0.28209479177387814f
#define NTHR  128
#define NVOX  64
#define NQUAD 8
#define NKS   5                          // k8 steps per quad (K=40)

#define XS_F2      (HZZ * HYY * XSTR)    // 1440 float2 per plane
#define YS_STRIDE  72                    // 64 vox + 8 pad
#define YS_FLOATS  (40 * YS_STRIDE)      // 2880
#define SMEM_FLOATS (2 * 2 * XS_F2 + YS_FLOATS)   // 5760 + 2880 = 8640
#define SMEM_BYTES  (SMEM_FLOATS * 4 + 128)       // ~34.7 KB -> 6 blocks/SM

typedef unsigned long long ull_t;

__device__ __host__ constexpr int p_of_r2(int r2) {
    return r2 <= 6 ? r2 : (r2 == 8 ? 7 : (r2 == 9 ? 8 : 9));
}

// B fragments: [quad][ks][nt][lane] -> float2 {b0hi, b1hi}
__device__ float2 g_Bf[NQUAD * NKS * 8 * 32];

__device__ __forceinline__ uint32_t tf32_rna(float x) {
    uint32_t r;
    asm("cvt.rna.tf32.f32 %0, %1;" : "=r"(r) : "f"(x));
    return r;
}

__device__ __forceinline__ void mma_tf32(float* c,
                                         uint32_t a0, uint32_t a1, uint32_t a2, uint32_t a3,
                                         uint32_t b0, uint32_t b1) {
    asm("mma.sync.aligned.m16n8k8.row.col.f32.tf32.tf32.f32 "
        "{%0,%1,%2,%3}, {%4,%5,%6,%7}, {%8,%9}, {%0,%1,%2,%3};"
        : "+f"(c[0]), "+f"(c[1]), "+f"(c[2]), "+f"(c[3])
        : "r"(a0), "r"(a1), "r"(a2), "r"(a3), "r"(b0), "r"(b1));
}

// ---------- prep: W[o][ci][p] -> B-fragment layout, Y0 folded, hi tf32 ----------
__global__ void bprep_kernel(const float* __restrict__ wg) {
    int idx = blockIdx.x * 256 + threadIdx.x;
    if (idx >= NQUAD * NKS * 8 * 32) return;
    int lane = idx & 31;
    int r    = idx >> 5;
    int nt   = r & 7;  r >>= 3;
    int ks   = r % NKS;
    int quad = r / NKS;
    int gid = lane >> 2, tidg = lane & 3;
    int o = nt * 8 + gid;
    auto getw = [&](int k) -> float {        // k in 0..39
        int ci = quad * 4 + k / 10;
        int p  = k % 10;
        return Y0C * wg[o * (NI * NP) + ci * NP + p];
    };
    float b0 = getw(ks * 8 + tidg);
    float b1 = getw(ks * 8 + tidg + 4);
    g_Bf[idx] = make_float2(__uint_as_float(tf32_rna(b0)),
                            __uint_as_float(tf32_rna(b1)));
}

// ---------- main ----------
__global__ void __launch_bounds__(NTHR, 6)
econv_kernel(const float* __restrict__ x,
             const float* __restrict__ bias,
             float* __restrict__ out)
{
    extern __shared__ float smem[];
    float2* xsp[2];                             // per-chpair halo planes
    xsp[0] = (float2*)smem;
    xsp[1] = xsp[0] + XS_F2;
    float* Ys = smem + 4 * XS_F2;               // [k][vox], stride YS_STRIDE

    const int tid  = threadIdx.x;
    const int wid  = tid >> 5;
    const int lid  = tid & 31;
    const int gid  = lid >> 2;
    const int tidg = lid & 3;
    const int b    = blockIdx.y;
    const int t    = blockIdx.x;                // 6x6x48 tiles
    const int tz   = t / 36;
    const int ty   = (t % 36) / 6;
    const int tx   = t % 6;
    const int z0   = tz, y0 = ty * TY, x0 = tx * TX;

    const size_t x_chan = (size_t)DIMS * DIMS * DIMS;
    const float* xb = x + (size_t)b * NI * x_chan;

    float acc[32];                              // 16 vox x 64 out per warp
    #pragma unroll
    for (int k = 0; k < 32; k++) acc[k] = 0.0f;

    // ---- halo load: 720 cells x 4 channels, coalesced over cells ----
    auto load_quad = [&](int quad) {
        const float* c0 = xb + (size_t)(4 * quad) * x_chan;
        float4 pre[6];
        #pragma unroll
        for (int k = 0; k < 6; k++) {
            int idx = tid + k * NTHR;
            float4 v = make_float4(0.f, 0.f, 0.f, 0.f);
            if (idx < HZZ * HYY * HXX) {
                int zz = idx / (HXX * HYY);
                int rr = idx % (HXX * HYY);
                int yy = rr / HXX, xx = rr % HXX;
                int gz = z0 + zz - 2, gy = y0 + yy - 2, gx = x0 + xx - 2;
                if ((unsigned)gz < (unsigned)DIMS &&
                    (unsigned)gy < (unsigned)DIMS &&
                    (unsigned)gx < (unsigned)DIMS) {
                    size_t off = ((size_t)gz * DIMS + gy) * DIMS + gx;
                    v.x = __ldg(&c0[off]);
                    v.y = __ldg(&c0[off + x_chan]);
                    v.z = __ldg(&c0[off + 2 * x_chan]);
                    v.w = __ldg(&c0[off + 3 * x_chan]);
                }
            }
            pre[k] = v;
        }
        #pragma unroll
        for (int k = 0; k < 6; k++) {
            int idx = tid + k * NTHR;
            if (idx < HZZ * HYY * HXX) {
                int zz = idx / (HXX * HYY);
                int rr = idx % (HXX * HYY);
                int yy = rr / HXX, xx = rr % HXX;
                int cell = (zz * HYY + yy) * XSTR + xx;
                xsp[0][cell] = make_float2(pre[k].x, pre[k].y);
                xsp[1][cell] = make_float2(pre[k].z, pre[k].w);
            }
        }
    };

    // ---- radial: 64 vox x 2 chpairs; 125 LDS.64, conflict-free ----
    auto radial = [&]() {
        const int cp = tid >> 6;                 // chpair 0/1
        const int v  = tid & 63;
        const int vy = v >> 3, vx = v & 7;
        const ull_t* xu = (const ull_t*)xsp[cp];
        ull_t yr[NP];
        #pragma unroll
        for (int p = 0; p < NP; p++) yr[p] = 0ULL;
        #pragma unroll
        for (int dz = 0; dz < 5; dz++) {
            #pragma unroll
            for (int dy = 0; dy < 5; dy++) {
                const ull_t* row = &xu[(dz * HYY + (vy + dy)) * XSTR + vx];
                #pragma unroll
                for (int dx = 0; dx < 5; dx++) {
                    const int p = p_of_r2((dz - 2) * (dz - 2) +
                                          (dy - 2) * (dy - 2) +
                                          (dx - 2) * (dx - 2));
                    asm("add.rn.f32x2 %0, %0, %1;" : "+l"(yr[p]) : "l"(row[dx]));
                }
            }
        }
        #pragma unroll
        for (int p = 0; p < NP; p++) {
            float2 a = *(float2*)&yr[p];
            Ys[(p + 20 * cp) * YS_STRIDE + v]      = a.x;  // ch 2cp
            Ys[(p + 10 + 20 * cp) * YS_STRIDE + v] = a.y;  // ch 2cp+1
        }
    };

    // ---- GEMM: 2-split tf32, warp = 16 vox x 64 out, K=40 ----
    auto gemm = [&](int quad) {
        const float2* bsrc = g_Bf + quad * (NKS * 8 * 32);
        const int vb = wid * 16 + gid;
        #pragma unroll
        for (int ks = 0; ks < NKS; ks++) {
            const float* yk = Ys + (ks * 8 + tidg) * YS_STRIDE;
            float a[4];
            a[0] = yk[vb];
            a[1] = yk[vb + 8];
            a[2] = yk[4 * YS_STRIDE + vb];
            a[3] = yk[4 * YS_STRIDE + vb + 8];
            uint32_t Ah[4], Al[4];
            #pragma unroll
            for (int r = 0; r < 4; r++) {
                Ah[r] = tf32_rna(a[r]);
                Al[r] = tf32_rna(a[r] - __uint_as_float(Ah[r]));
            }
            #pragma unroll
            for (int nt = 0; nt < 8; nt++) {
                float2 bf = __ldg(&bsrc[(ks * 8 + nt) * 32 + lid]);
                uint32_t b0h = __float_as_uint(bf.x);
                uint32_t b1h = __float_as_uint(bf.y);
                float* c = &acc[nt * 4];
                mma_tf32(c, Ah[0], Ah[1], Ah[2], Ah[3], b0h, b1h);
                mma_tf32(c, Al[0], Al[1], Al[2], Al[3], b0h, b1h);
            }
        }
    };

    // ---- prologue ----
    load_quad(0);
    __syncthreads();                 // xs(0) visible
    radial();                        // Ys(0)

    // ---- main loop over 8 quads (2 bars/iter, phase-pure regions) ----
    #pragma unroll 1
    for (int q = 0; q < NQUAD; q++) {
        __syncthreads();             // Ys(q) visible; radial reads of xs done
        gemm(q);
        if (q + 1 < NQUAD) {
            load_quad(q + 1);        // writes xs (gemm doesn't touch it)
            __syncthreads();         // xs(q+1) visible; gemm done with Ys
            radial();                // Ys(q+1)
        }
    }

    // ---- epilogue: stage via smem (aliases Ys) for vectorized stores ----
    __syncthreads();
    float* stage = Ys;               // [c16][vox], stride YS_STRIDE
    const int vb = wid * 16 + gid;
    #pragma unroll 1
    for (int chunk = 0; chunk < 4; chunk++) {
        if (chunk) __syncthreads();
        #pragma unroll
        for (int nt2 = 0; nt2 < 2; nt2++) {
            const int nt = chunk * 2 + nt2;
            #pragma unroll
            for (int r = 0; r < 4; r++) {
                int vox = vb + ((r >> 1) << 3);
                int c16 = nt2 * 8 + 2 * tidg + (r & 1);
                stage[c16 * YS_STRIDE + vox] = acc[nt * 4 + r];
            }
        }
        __syncthreads();
        // 128 threads: o16 = tid>>3 (0..15), vy = tid&7 -> 8 floats each
        {
            const int o16 = tid >> 3;
            const int vy  = tid & 7;
            const int o   = chunk * 16 + o16;
            const float bb = __ldg(&bias[o]);
            float4 v0 = *(float4*)&stage[o16 * YS_STRIDE + vy * 8];
            float4 v1 = *(float4*)&stage[o16 * YS_STRIDE + vy * 8 + 4];
            v0.x += bb; v0.y += bb; v0.z += bb; v0.w += bb;
            v1.x += bb; v1.y += bb; v1.z += bb; v1.w += bb;
            float* dst = out + ((size_t)b * NO + o) * x_chan
                             + ((size_t)z0 * DIMS + (y0 + vy)) * DIMS + x0;
            *(float4*)&dst[0] = v0;
            *(float4*)&dst[4] = v1;
        }
    }
}

extern "C" void kernel_launch(void* const* d_in, const int* in_sizes, int n_in,
                              void* d_out, int out_size)
{
    const float* x    = (const float*)d_in[0];   // [2,32,1,48,48,48]
    const float* w    = (const float*)d_in[1];   // [64,32,1,1,1,10]
    const float* bias = (const float*)d_in[2];   // [64]
    float* out = (float*)d_out;                  // [2,64,1,48,48,48]

    bprep_kernel<<<(NQUAD * NKS * 8 * 32 + 255) / 256, 256>>>(w);

    cudaFuncSetAttribute(econv_kernel,
                         cudaFuncAttributeMaxDynamicSharedMemorySize, SMEM_BYTES);
    dim3 grid(1728, 2);   // 6x6x48 spatial tiles x batch
    econv_kernel<<<grid, NTHR, SMEM_BYTES>>>(x, bias, out);
}

// round 15
// speedup vs baseline: 1.1458x; 1.0184x over previous
#include <cuda_runtime.h>
#include <cstdint>

// EquiLocalPatOrientConvolution: B=2, I=32, O=64, D=H=W=48, K=5 (pad 2).
// v15 = v12 (quad packing, 2-split tf32 mma, 2-bar phase-pure loop) with
// y-pair radial: thread = (ch-half, voxel-pair); 150 LDS.64 serve 2 voxels
// (cells shared between y-adjacent voxels) -> -40% radial crossbar bytes.

#define DIMS  48
#define TX    8
#define TY    8
#define TZ    2
#define HX    12
#define HY    12
#define HZ    6
#define NI    32
#define NO    64
#define NP    10
#define Y0C   0.28209479177387814f
#define NTHR  128
#define NQUAD 8
#define NKS   5                          // k8 steps per quad (K=40)

#define XS_CELLS   (HZ * HY * HX)        // 864 float4 cells per buffer
#define YS_STRIDE  136                   // 128 vox + 8 pad
#define YS_ROWS    40                    // K=40, exact
#define YS_FLOATS  (YS_ROWS * YS_STRIDE)
#define SMEM_FLOATS (2 * 4 * XS_CELLS + YS_FLOATS)
#define SMEM_BYTES  (SMEM_FLOATS * 4 + 256)   // ~49.7 KB -> 4 blocks/SM

typedef unsigned long long ull_t;

__device__ __host__ constexpr int p_of_r2(int r2) {
    return r2 <= 6 ? r2 : (r2 == 8 ? 7 : (r2 == 9 ? 8 : 9));
}

// B fragments: [quad][ks][nt][lane] -> float2 {b0hi, b1hi}
__device__ float2 g_Bf[NQUAD * NKS * 8 * 32];

__device__ __forceinline__ uint32_t tf32_rna(float x) {
    uint32_t r;
    asm("cvt.rna.tf32.f32 %0, %1;" : "=r"(r) : "f"(x));
    return r;
}

__device__ __forceinline__ ull_t addx2(ull_t a, ull_t b) {
    ull_t r;
    asm("add.rn.f32x2 %0, %1, %2;" : "=l"(r) : "l"(a), "l"(b));
    return r;
}

__device__ __forceinline__ void mma_tf32(float* c,
                                         uint32_t a0, uint32_t a1, uint32_t a2, uint32_t a3,
                                         uint32_t b0, uint32_t b1) {
    asm("mma.sync.aligned.m16n8k8.row.col.f32.tf32.tf32.f32 "
        "{%0,%1,%2,%3}, {%4,%5,%6,%7}, {%8,%9}, {%0,%1,%2,%3};"
        : "+f"(c[0]), "+f"(c[1]), "+f"(c[2]), "+f"(c[3])
        : "r"(a0), "r"(a1), "r"(a2), "r"(a3), "r"(b0), "r"(b1));
}

// ---------- prep: W[o][ci][p] -> B-fragment layout, Y0 folded, hi tf32 ----------
__global__ void bprep_kernel(const float* __restrict__ wg) {
    int idx = blockIdx.x * 256 + threadIdx.x;
    if (idx >= NQUAD * NKS * 8 * 32) return;
    int lane = idx & 31;
    int r    = idx >> 5;
    int nt   = r & 7;  r >>= 3;
    int ks   = r % NKS;
    int quad = r / NKS;
    int gid = lane >> 2, tidg = lane & 3;
    int o = nt * 8 + gid;
    auto getw = [&](int k) -> float {        // k in 0..39
        int ci = quad * 4 + k / 10;
        int p  = k % 10;
        return Y0C * wg[o * (NI * NP) + ci * NP + p];
    };
    float b0 = getw(ks * 8 + tidg);
    float b1 = getw(ks * 8 + tidg + 4);
    g_Bf[idx] = make_float2(__uint_as_float(tf32_rna(b0)),
                            __uint_as_float(tf32_rna(b1)));
}

// ---------- main ----------
__global__ void __launch_bounds__(NTHR, 4)
econv_kernel(const float* __restrict__ x,
             const float* __restrict__ bias,
             float* __restrict__ out)
{
    extern __shared__ float smem[];
    float4* xs[2];
    xs[0] = (float4*)smem;
    xs[1] = xs[0] + XS_CELLS;
    float* Ys = smem + 8 * XS_CELLS;            // [k][vox], stride YS_STRIDE

    const int tid  = threadIdx.x;
    const int wid  = tid >> 5;
    const int lid  = tid & 31;
    const int gid  = lid >> 2;
    const int tidg = lid & 3;
    const int b    = blockIdx.y;
    const int t    = blockIdx.x;                // 6x6x24
    const int tz   = t / 36;
    const int ty   = (t % 36) / 6;
    const int tx   = t % 6;
    const int z0   = tz * TZ, y0 = ty * TY, x0 = tx * TX;

    const size_t x_chan = (size_t)DIMS * DIMS * DIMS;
    const float* xb = x + (size_t)b * NI * x_chan;

    float acc[64];
    #pragma unroll
    for (int k = 0; k < 64; k++) acc[k] = 0.0f;

    // ---- halo prefetch + commit for a quad (4 channels), coalesced ----
    auto load_quad = [&](int quad, float4* dst) {
        const float* c0 = xb + (size_t)(4 * quad) * x_chan;
        float4 pre[7];
        #pragma unroll
        for (int k = 0; k < 7; k++) {
            int idx = tid + k * NTHR;
            float4 v = make_float4(0.f, 0.f, 0.f, 0.f);
            if (idx < XS_CELLS) {
                int zz = idx / (HX * HY);
                int rr = idx % (HX * HY);
                int yy = rr / HX, xx = rr % HX;
                int gz = z0 + zz - 2, gy = y0 + yy - 2, gx = x0 + xx - 2;
                if ((unsigned)gz < (unsigned)DIMS &&
                    (unsigned)gy < (unsigned)DIMS &&
                    (unsigned)gx < (unsigned)DIMS) {
                    size_t off = ((size_t)gz * DIMS + gy) * DIMS + gx;
                    v.x = __ldg(&c0[off]);
                    v.y = __ldg(&c0[off + x_chan]);
                    v.z = __ldg(&c0[off + 2 * x_chan]);
                    v.w = __ldg(&c0[off + 3 * x_chan]);
                }
            }
            pre[k] = v;
        }
        #pragma unroll
        for (int k = 0; k < 7; k++) {
            int idx = tid + k * NTHR;
            if (idx < XS_CELLS) dst[idx] = pre[k];   // STS.128
        }
    };

    // ---- y-pair radial: thread = (ch-half h, voxel-pair pp) ----
    // 150 LDS.64 cover both voxels (vy=2py, 2py+1); 250 compile-time adds.
    auto radial = [&](const float4* xsrc) {
        const int h  = tid >> 6;                 // 0: ch0/1, 1: ch2/3
        const int pp = tid & 63;
        const int vz = pp >> 5, py = (pp >> 3) & 3, vx = pp & 7;
        const ull_t* xu = (const ull_t*)xsrc;
        ull_t y0[NP], y1[NP];
        #pragma unroll
        for (int p = 0; p < NP; p++) { y0[p] = 0ULL; y1[p] = 0ULL; }
        #pragma unroll
        for (int dz = 0; dz < 5; dz++) {
            #pragma unroll
            for (int dyp = 0; dyp < 6; dyp++) {
                const int cellbase =
                    ((vz + dz) * HY + (2 * py + dyp)) * HX + vx;
                #pragma unroll
                for (int dx = 0; dx < 5; dx++) {
                    const int q1 = (dz - 2) * (dz - 2) + (dx - 2) * (dx - 2);
                    ull_t v = xu[2 * (cellbase + dx) + h];   // LDS.64
                    if (dyp <= 4) {                          // vox0: dy = dyp-2
                        const int p0 = p_of_r2(q1 + (dyp - 2) * (dyp - 2));
                        y0[p0] = addx2(y0[p0], v);
                    }
                    if (dyp >= 1) {                          // vox1: dy = dyp-3
                        const int p1 = p_of_r2(q1 + (dyp - 3) * (dyp - 3));
                        y1[p1] = addx2(y1[p1], v);
                    }
                }
            }
        }
        const int v0 = vz * 64 + (2 * py) * 8 + vx;
        const int v1 = v0 + 8;
        #pragma unroll
        for (int p = 0; p < NP; p++) {
            float2 a = *(float2*)&y0[p];
            float2 c = *(float2*)&y1[p];
            Ys[(p + 20 * h) * YS_STRIDE + v0]      = a.x;  // ch 2h
            Ys[(p + 10 + 20 * h) * YS_STRIDE + v0] = a.y;  // ch 2h+1
            Ys[(p + 20 * h) * YS_STRIDE + v1]      = c.x;
            Ys[(p + 10 + 20 * h) * YS_STRIDE + v1] = c.y;
        }
    };

    // ---- GEMM: 2-split tf32 mma over this quad's K=40 (5 exact k8 steps) ----
    auto gemm = [&](int quad) {
        const float2* bsrc = g_Bf + quad * (NKS * 8 * 32);
        #pragma unroll
        for (int ks = 0; ks < NKS; ks++) {
            uint32_t Ah[2][4], Al[2][4];
            #pragma unroll
            for (int mt = 0; mt < 2; mt++) {
                const int vb = wid * 32 + mt * 16 + gid;
                const float* yk = Ys + (ks * 8 + tidg) * YS_STRIDE;
                float a[4];
                a[0] = yk[vb];
                a[1] = yk[vb + 8];
                a[2] = yk[4 * YS_STRIDE + vb];
                a[3] = yk[4 * YS_STRIDE + vb + 8];
                #pragma unroll
                for (int r = 0; r < 4; r++) {
                    Ah[mt][r] = tf32_rna(a[r]);
                    Al[mt][r] = tf32_rna(a[r] - __uint_as_float(Ah[mt][r]));
                }
            }
            #pragma unroll
            for (int nt = 0; nt < 8; nt++) {
                float2 bf = __ldg(&bsrc[(ks * 8 + nt) * 32 + lid]);
                uint32_t b0h = __float_as_uint(bf.x);
                uint32_t b1h = __float_as_uint(bf.y);
                #pragma unroll
                for (int mt = 0; mt < 2; mt++) {
                    float* c = &acc[(mt * 8 + nt) * 4];
                    mma_tf32(c, Ah[mt][0], Ah[mt][1], Ah[mt][2], Ah[mt][3], b0h, b1h);
                    mma_tf32(c, Al[mt][0], Al[mt][1], Al[mt][2], Al[mt][3], b0h, b1h);
                }
            }
        }
    };

    // ---- prologue ----
    load_quad(0, xs[0]);
    __syncthreads();                 // xs(0) visible
    radial(xs[0]);                   // Ys(0)

    // ---- main loop over 8 quads (2 bars/iter, phase-pure regions) ----
    #pragma unroll 1
    for (int q = 0; q < NQUAD; q++) {
        __syncthreads();             // Ys(q) visible
        gemm(q);
        if (q + 1 < NQUAD) {
            load_quad(q + 1, xs[(q + 1) & 1]);
            __syncthreads();         // xs(q+1) visible; gemm done with Ys
            radial(xs[(q + 1) & 1]); // Ys(q+1)
        }
    }

    // ---- epilogue: stage through smem (aliases Ys) for coalesced stores ----
    __syncthreads();
    float* stage = Ys;
    #pragma unroll 1
    for (int chunk = 0; chunk < 4; chunk++) {
        if (chunk) __syncthreads();
        #pragma unroll
        for (int mt = 0; mt < 2; mt++) {
            #pragma unroll
            for (int nt2 = 0; nt2 < 2; nt2++) {
                const int nt = chunk * 2 + nt2;
                #pragma unroll
                for (int r = 0; r < 4; r++) {
                    int vox = wid * 32 + mt * 16 + gid + ((r >> 1) << 3);
                    int c16 = nt2 * 8 + 2 * tidg + (r & 1);
                    stage[c16 * YS_STRIDE + vox] = acc[(mt * 8 + nt) * 4 + r];
                }
            }
        }
        __syncthreads();
        #pragma unroll
        for (int j = 0; j < 4; j++) {
            const int o16  = j * 4 + wid;
            const int row  = lid >> 1;
            const int half = lid & 1;
            const int o    = chunk * 16 + o16;
            const float bb = __ldg(&bias[o]);
            float4 v = *(float4*)&stage[o16 * YS_STRIDE + row * 8 + half * 4];
            v.x += bb; v.y += bb; v.z += bb; v.w += bb;
            const int gz = z0 + (row >> 3), gy = y0 + (row & 7);
            float* dst = out + ((size_t)b * NO + o) * x_chan
                             + ((size_t)gz * DIMS + gy) * DIMS + x0 + half * 4;
            *(float4*)dst = v;
        }
    }
}

extern "C" void kernel_launch(void* const* d_in, const int* in_sizes, int n_in,
                              void* d_out, int out_size)
{
    const float* x    = (const float*)d_in[0];   // [2,32,1,48,48,48]
    const float* w    = (const float*)d_in[1];   // [64,32,1,1,1,10]
    const float* bias = (const float*)d_in[2];   // [64]
    float* out = (float*)d_out;                  // [2,64,1,48,48,48]

    bprep_kernel<<<(NQUAD * NKS * 8 * 32 + 255) / 256, 256>>>(w);

    cudaFuncSetAttribute(econv_kernel,
                         cudaFuncAttributeMaxDynamicSharedMemorySize, SMEM_BYTES);
    dim3 grid(864, 2);   // 6x6x24 spatial tiles x batch
    econv_kernel<<<grid, NTHR, SMEM_BYTES>>>(x, bias, out);
}

// round 16
// speedup vs baseline: 1.2879x; 1.1241x over previous
#include <cuda_runtime.h>
#include <cstdint>

// EquiLocalPatOrientConvolution: B=2, I=32, O=64, D=H=W=48, K=5 (pad 2).
// v16 = v12 per-thread structure at 2x scale: 256 threads, 8x8x4 tile.
// Quad channel packing, direct conflict-free 125-tap LDS.128 radial,
// 2-split tf32 mma (K=40 exact), permuted Ys for float2 A-loads.

#define DIMS  48
#define TX    8
#define TY    8
#define TZ    4
#define HX    12
#define HY    12
#define HZ    8
#define NI    32
#define NO    64
#define NP    10
#define Y0C   0.28209479177387814f
#define NTHR  256
#define NQUAD 8
#define NKS   5                          // k8 steps per quad (K=40)

#define XS_CELLS   (HZ * HY * HX)        // 1152 float4 cells per buffer
#define YS_STRIDE  264                   // 256 vox + 8 pad (264/2 mod 16 = 4)
#define YS_FLOATS  (40 * YS_STRIDE)      // 10560
#define SMEM_FLOATS (2 * 4 * XS_CELLS + YS_FLOATS)  // 9216 + 10560
#define SMEM_BYTES  (SMEM_FLOATS * 4 + 256)         // ~79.4 KB -> 2 blocks/SM

typedef unsigned long long ull_t;

__device__ __host__ constexpr int p_of_r2(int r2) {
    return r2 <= 6 ? r2 : (r2 == 8 ? 7 : (r2 == 9 ? 8 : 9));
}

// B fragments: [quad][ks][nt][lane] -> float2 {b0hi, b1hi}
__device__ float2 g_Bf[NQUAD * NKS * 8 * 32];

__device__ __forceinline__ uint32_t tf32_rna(float x) {
    uint32_t r;
    asm("cvt.rna.tf32.f32 %0, %1;" : "=r"(r) : "f"(x));
    return r;
}

__device__ __forceinline__ void mma_tf32(float* c,
                                         uint32_t a0, uint32_t a1, uint32_t a2, uint32_t a3,
                                         uint32_t b0, uint32_t b1) {
    asm("mma.sync.aligned.m16n8k8.row.col.f32.tf32.tf32.f32 "
        "{%0,%1,%2,%3}, {%4,%5,%6,%7}, {%8,%9}, {%0,%1,%2,%3};"
        : "+f"(c[0]), "+f"(c[1]), "+f"(c[2]), "+f"(c[3])
        : "r"(a0), "r"(a1), "r"(a2), "r"(a3), "r"(b0), "r"(b1));
}

// ---------- prep: W[o][ci][p] -> B-fragment layout, Y0 folded, hi tf32 ----------
__global__ void bprep_kernel(const float* __restrict__ wg) {
    int idx = blockIdx.x * 256 + threadIdx.x;
    if (idx >= NQUAD * NKS * 8 * 32) return;
    int lane = idx & 31;
    int r    = idx >> 5;
    int nt   = r & 7;  r >>= 3;
    int ks   = r % NKS;
    int quad = r / NKS;
    int gid = lane >> 2, tidg = lane & 3;
    int o = nt * 8 + gid;
    auto getw = [&](int k) -> float {        // k in 0..39
        int ci = quad * 4 + k / 10;
        int p  = k % 10;
        return Y0C * wg[o * (NI * NP) + ci * NP + p];
    };
    float b0 = getw(ks * 8 + tidg);
    float b1 = getw(ks * 8 + tidg + 4);
    g_Bf[idx] = make_float2(__uint_as_float(tf32_rna(b0)),
                            __uint_as_float(tf32_rna(b1)));
}

// ---------- main ----------
__global__ void __launch_bounds__(NTHR, 2)
econv_kernel(const float* __restrict__ x,
             const float* __restrict__ bias,
             float* __restrict__ out)
{
    extern __shared__ float smem[];
    float4* xs[2];
    xs[0] = (float4*)smem;
    xs[1] = xs[0] + XS_CELLS;
    float* Ys = smem + 8 * XS_CELLS;            // [k][perm(vox)], stride 264

    const int tid  = threadIdx.x;
    const int wid  = tid >> 5;                  // 0..7
    const int lid  = tid & 31;
    const int gid  = lid >> 2;
    const int tidg = lid & 3;
    const int b    = blockIdx.y;
    const int t    = blockIdx.x;                // 6x6x12
    const int tz   = t / 36;
    const int ty   = (t % 36) / 6;
    const int tx   = t % 6;
    const int z0   = tz * TZ, y0 = ty * TY, x0 = tx * TX;

    const size_t x_chan = (size_t)DIMS * DIMS * DIMS;
    const float* xb = x + (size_t)b * NI * x_chan;

    float acc[64];
    #pragma unroll
    for (int k = 0; k < 64; k++) acc[k] = 0.0f;

    // ---- halo prefetch + commit for a quad (4 channels), coalesced ----
    auto load_quad = [&](int quad, float4* dst) {
        const float* c0 = xb + (size_t)(4 * quad) * x_chan;
        float4 pre[5];
        #pragma unroll
        for (int k = 0; k < 5; k++) {
            int idx = tid + k * NTHR;
            float4 v = make_float4(0.f, 0.f, 0.f, 0.f);
            if (idx < XS_CELLS) {
                int zz = idx / (HX * HY);
                int rr = idx % (HX * HY);
                int yy = rr / HX, xx = rr % HX;
                int gz = z0 + zz - 2, gy = y0 + yy - 2, gx = x0 + xx - 2;
                if ((unsigned)gz < (unsigned)DIMS &&
                    (unsigned)gy < (unsigned)DIMS &&
                    (unsigned)gx < (unsigned)DIMS) {
                    size_t off = ((size_t)gz * DIMS + gy) * DIMS + gx;
                    v.x = __ldg(&c0[off]);
                    v.y = __ldg(&c0[off + x_chan]);
                    v.z = __ldg(&c0[off + 2 * x_chan]);
                    v.w = __ldg(&c0[off + 3 * x_chan]);
                }
            }
            pre[k] = v;
        }
        #pragma unroll
        for (int k = 0; k < 5; k++) {
            int idx = tid + k * NTHR;
            if (idx < XS_CELLS) dst[idx] = pre[k];   // STS.128
        }
    };

    // Ys permutation: vox = base16 + 8s + g  ->  base16 + 2g + s
    const int pv = (tid & ~15) | ((tid & 7) << 1) | ((tid >> 3) & 1);

    // ---- radial: 1 voxel x 4 channels, 125 LDS.128, conflict-free ----
    auto radial = [&](const float4* xsrc) {
        const int vz = tid >> 6, vy = (tid >> 3) & 7, vx = tid & 7;
        ull_t y01[NP], y23[NP];
        #pragma unroll
        for (int p = 0; p < NP; p++) { y01[p] = 0ULL; y23[p] = 0ULL; }
        #pragma unroll
        for (int dz = 0; dz < 5; dz++) {
            #pragma unroll
            for (int dy = 0; dy < 5; dy++) {
                const float4* row = &xsrc[((vz + dz) * HY + (vy + dy)) * HX + vx];
                #pragma unroll
                for (int dx = 0; dx < 5; dx++) {
                    const int p = p_of_r2((dz - 2) * (dz - 2) +
                                          (dy - 2) * (dy - 2) +
                                          (dx - 2) * (dx - 2));
                    union { float4 f; ull_t u[2]; } c;
                    c.f = row[dx];
                    asm("add.rn.f32x2 %0, %0, %1;" : "+l"(y01[p]) : "l"(c.u[0]));
                    asm("add.rn.f32x2 %0, %0, %1;" : "+l"(y23[p]) : "l"(c.u[1]));
                }
            }
        }
        #pragma unroll
        for (int p = 0; p < NP; p++) {
            float2 a = *(float2*)&y01[p];
            float2 d = *(float2*)&y23[p];
            Ys[p * YS_STRIDE + pv]        = a.x;   // ch0 -> k rows 0..9
            Ys[(p + 10) * YS_STRIDE + pv] = a.y;   // ch1 -> k rows 10..19
            Ys[(p + 20) * YS_STRIDE + pv] = d.x;   // ch2 -> k rows 20..29
            Ys[(p + 30) * YS_STRIDE + pv] = d.y;   // ch3 -> k rows 30..39
        }
    };

    // ---- GEMM: 2-split tf32 mma, warp = 32 vox x 64 out, K=40 ----
    auto gemm = [&](int quad) {
        const float2* bsrc = g_Bf + quad * (NKS * 8 * 32);
        #pragma unroll
        for (int ks = 0; ks < NKS; ks++) {
            uint32_t Ah[2][4], Al[2][4];
            #pragma unroll
            for (int mt = 0; mt < 2; mt++) {
                const int base = wid * 32 + mt * 16 + 2 * gid;
                const float* yk = Ys + (ks * 8 + tidg) * YS_STRIDE;
                float2 a01 = *(const float2*)&yk[base];                  // rows g, g+8
                float2 a23 = *(const float2*)&yk[4 * YS_STRIDE + base];  // k+4
                float a[4] = { a01.x, a01.y, a23.x, a23.y };
                #pragma unroll
                for (int r = 0; r < 4; r++) {
                    Ah[mt][r] = tf32_rna(a[r]);
                    Al[mt][r] = tf32_rna(a[r] - __uint_as_float(Ah[mt][r]));
                }
            }
            #pragma unroll
            for (int nt = 0; nt < 8; nt++) {
                float2 bf = __ldg(&bsrc[(ks * 8 + nt) * 32 + lid]);
                uint32_t b0h = __float_as_uint(bf.x);
                uint32_t b1h = __float_as_uint(bf.y);
                #pragma unroll
                for (int mt = 0; mt < 2; mt++) {
                    float* c = &acc[(mt * 8 + nt) * 4];
                    mma_tf32(c, Ah[mt][0], Ah[mt][1], Ah[mt][2], Ah[mt][3], b0h, b1h);
                    mma_tf32(c, Al[mt][0], Al[mt][1], Al[mt][2], Al[mt][3], b0h, b1h);
                }
            }
        }
    };

    // ---- prologue ----
    load_quad(0, xs[0]);
    __syncthreads();                 // xs(0) visible
    radial(xs[0]);                   // Ys(0)

    // ---- main loop over 8 quads (2 bars/iter, phase-pure regions) ----
    #pragma unroll 1
    for (int q = 0; q < NQUAD; q++) {
        __syncthreads();             // Ys(q) visible
        gemm(q);
        if (q + 1 < NQUAD) {
            load_quad(q + 1, xs[(q + 1) & 1]);
            __syncthreads();         // xs(q+1) visible; gemm done with Ys
            radial(xs[(q + 1) & 1]); // Ys(q+1)
        }
    }

    // ---- epilogue: stage through smem (aliases Ys) for coalesced stores ----
    __syncthreads();
    float* stage = Ys;               // [c16][vox 0..255], stride YS_STRIDE
    #pragma unroll 1
    for (int chunk = 0; chunk < 4; chunk++) {
        if (chunk) __syncthreads();
        #pragma unroll
        for (int mt = 0; mt < 2; mt++) {
            #pragma unroll
            for (int nt2 = 0; nt2 < 2; nt2++) {
                const int nt = chunk * 2 + nt2;
                #pragma unroll
                for (int r = 0; r < 4; r++) {
                    int vox = wid * 32 + mt * 16 + gid + ((r >> 1) << 3);
                    int c16 = nt2 * 8 + 2 * tidg + (r & 1);
                    stage[c16 * YS_STRIDE + vox] = acc[(mt * 8 + nt) * 4 + r];
                }
            }
        }
        __syncthreads();
        // 4 rounds x 256 threads: one float4 each (slot = q mod 8, bijective)
        #pragma unroll
        for (int round = 0; round < 4; round++) {
            const int idx = round * 256 + tid;
            const int o16 = idx >> 6;            // 0..15
            const int q4  = idx & 63;            // float4 group over 256 vox
            const int o   = chunk * 16 + o16;
            const float bb = __ldg(&bias[o]);
            float4 v = *(float4*)&stage[o16 * YS_STRIDE + q4 * 4];
            v.x += bb; v.y += bb; v.z += bb; v.w += bb;
            const int gz = z0 + (q4 >> 4);
            const int gy = y0 + ((q4 >> 1) & 7);
            const int gx = x0 + (q4 & 1) * 4;
            float* dst = out + ((size_t)b * NO + o) * x_chan
                             + ((size_t)gz * DIMS + gy) * DIMS + gx;
            *(float4*)dst = v;
        }
    }
}

extern "C" void kernel_launch(void* const* d_in, const int* in_sizes, int n_in,
                              void* d_out, int out_size)
{
    const float* x    = (const float*)d_in[0];   // [2,32,1,48,48,48]
    const float* w    = (const float*)d_in[1];   // [64,32,1,1,1,10]
    const float* bias = (const float*)d_in[2];   // [64]
    float* out = (float*)d_out;                  // [2,64,1,48,48,48]

    bprep_kernel<<<(NQUAD * NKS * 8 * 32 + 255) / 256, 256>>>(w);

    cudaFuncSetAttribute(econv_kernel,
                         cudaFuncAttributeMaxDynamicSharedMemorySize, SMEM_BYTES);
    dim3 grid(432, 2);   // 6x6x12 spatial tiles x batch
    econv_kernel<<<grid, NTHR, SMEM_BYTES>>>(x, bias, out);
}